// round 16
// baseline (speedup 1.0000x reference)
#include <cuda_runtime.h>
#include <cuda_fp16.h>
#include <cstdint>

// ---------------------------------------------------------------------------
// Dilated attention = sum of 4 dense flash-attention sub-problems over strided
// row subsets (B=2, S=2048, H=8, D=64):
//   cls0: q_start=0,    k_start=0, dil=1, rows=2048, Nk=2048
//   cls1: q_start=0,    k_start=0, dil=2, rows=512,  Nk=1024
//   cls2: q_start=1025, k_start=1, dil=2, rows=512,  Nk=1024
//   cls3: q_start=0,    k_start=0, dil=4, rows=512,  Nk=512
// prepass: K/V -> f16 once AND zero-fills out. fa_dil: all classes accumulate
// straight into out with red.global.add.v2.f32 (no scratch, no combine pass).
// BN=128 key-tiles processed as two 64-key halves with ONE wait+barrier per
// tile (halves the sync overhead). 4 warps x 32 q-rows (two m16 subtiles),
// mma.sync m16n8k16 fp16 (fp32 accum), fixed-shift softmax, ones-MMA row sums.
// ---------------------------------------------------------------------------

#define TOK    512        // H*D elements per token (f32 in, f16 in g_k16/v16)
#define BM     128        // queries per CTA (4 warps x 32 rows)
#define BN     128        // keys per tile (two 64-key halves)
#define NTH    128
#define STRIDE 72         // halfs per f16 smem row (conflict-free ldmatrix)

// dynamic smem layout (bytes)
#define SM_Q    0                                  // 128*72*2       = 18432
#define SM_K    18432                              // 2 * 128*72*2   = 36864
#define SM_V    (SM_K + 36864)                     // 36864
#define SM_TOT  (SM_V + 36864)                     // 92160

#define QSCALE 0.18033688f    // 0.125 * log2(e)
#define SHIFT  8.65617025f    // 6 * log2(e)
#define ONESH2 0x3C003C00u    // half2(1.0, 1.0)

// f16 copies of K and V (same [B,S,H,D] linear layout as the f32 inputs)
__device__ __half g_k16[2 * 2048 * 8 * 64];
__device__ __half g_v16[2 * 2048 * 8 * 64];

// ---- helpers --------------------------------------------------------------
__device__ __forceinline__ uint32_t smem_u32(const void* p) {
    uint32_t a;
    asm("{ .reg .u64 t; cvta.to.shared.u64 t, %1; cvt.u32.u64 %0, t; }"
        : "=r"(a) : "l"(p));
    return a;
}
__device__ __forceinline__ float ex2(float x) {
    float y; asm("ex2.approx.ftz.f32 %0, %1;" : "=f"(y) : "f"(x)); return y;
}
__device__ __forceinline__ uint32_t f16x2(float hi, float lo) {
    uint32_t r;
    asm("cvt.rn.f16x2.f32 %0, %1, %2;" : "=r"(r) : "f"(hi), "f"(lo));
    return r;
}
__device__ __forceinline__ void red2(float* a, float x, float y) {
    asm volatile("red.global.add.v2.f32 [%0], {%1, %2};"
                 :: "l"(a), "f"(x), "f"(y) : "memory");
}
__device__ __forceinline__ void cpa16(uint32_t saddr, const void* gaddr) {
    asm volatile("cp.async.cg.shared.global [%0], [%1], 16;"
                 :: "r"(saddr), "l"(gaddr));
}
__device__ __forceinline__ void cpa_commit() {
    asm volatile("cp.async.commit_group;");
}
template <int N> __device__ __forceinline__ void cpa_wait() {
    asm volatile("cp.async.wait_group %0;" :: "n"(N));
}
__device__ __forceinline__ void sts64(uint32_t a, uint32_t x, uint32_t y) {
    asm volatile("st.shared.v2.b32 [%0], {%1, %2};" :: "r"(a), "r"(x), "r"(y));
}
__device__ __forceinline__ void ldmx4(uint32_t r[4], uint32_t a) {
    asm volatile("ldmatrix.sync.aligned.m8n8.x4.shared.b16 {%0,%1,%2,%3}, [%4];"
        : "=r"(r[0]), "=r"(r[1]), "=r"(r[2]), "=r"(r[3]) : "r"(a));
}
__device__ __forceinline__ void ldmx4t(uint32_t r[4], uint32_t a) {
    asm volatile("ldmatrix.sync.aligned.m8n8.x4.trans.shared.b16 {%0,%1,%2,%3}, [%4];"
        : "=r"(r[0]), "=r"(r[1]), "=r"(r[2]), "=r"(r[3]) : "r"(a));
}
__device__ __forceinline__ void mma16816(float c[4], const uint32_t a[4],
                                         uint32_t b0, uint32_t b1) {
    asm volatile(
        "mma.sync.aligned.m16n8k16.row.col.f32.f16.f16.f32 "
        "{%0,%1,%2,%3}, {%4,%5,%6,%7}, {%8,%9}, {%0,%1,%2,%3};"
        : "+f"(c[0]), "+f"(c[1]), "+f"(c[2]), "+f"(c[3])
        : "r"(a[0]), "r"(a[1]), "r"(a[2]), "r"(a[3]), "r"(b0), "r"(b1));
}

// ---- pre-pass: K/V f32->f16 convert + zero-fill out -----------------------
__global__ void __launch_bounds__(256)
prepass(const float4* __restrict__ k, const float4* __restrict__ v,
        float4* __restrict__ out, int total8, int total4)
{
    int i = blockIdx.x * 256 + threadIdx.x;
    if (i < 2 * total8) {                      // convert K or V (16B chunk)
        bool isV = i >= total8;
        int jj = isV ? i - total8 : i;
        const float4* s = (isV ? v : k) + (size_t)jj * 2;
        float4 a = s[0], b = s[1];
        uint4 o;
        o.x = f16x2(a.y, a.x); o.y = f16x2(a.w, a.z);
        o.z = f16x2(b.y, b.x); o.w = f16x2(b.w, b.z);
        ((uint4*)(isV ? g_v16 : g_k16))[jj] = o;
    } else {                                   // zero 16B of out
        int jj = i - 2 * total8;
        if (jj < total4) out[jj] = make_float4(0.f, 0.f, 0.f, 0.f);
    }
}

// ---------------------------------------------------------------------------

__global__ void __launch_bounds__(NTH, 2)
fa_dil(const float* __restrict__ qg, float* __restrict__ outg)
{
    extern __shared__ char smem[];
    const uint32_t sb = smem_u32(smem);

    const int tid = threadIdx.x;
    const int wid = tid >> 5;            // 0..3, owns rows wid*32..wid*32+31
    const int lane = tid & 31;
    const int by = blockIdx.y;           // class/qtile (cls0 lowest bids)
    const int bz = blockIdx.x >> 3;      // H = 8
    const int h  = blockIdx.x & 7;

    // ---- decode component class ----
    int cls, qtile;
    if (by < 16)      { cls = 0; qtile = by; }
    else if (by < 20) { cls = 1; qtile = by - 16; }
    else if (by < 24) { cls = 2; qtile = by - 20; }
    else              { cls = 3; qtile = by - 24; }
    const int q_start = (cls == 2) ? 1025 : 0;
    const int k_start = (cls == 2) ? 1 : 0;
    const int dil = (cls == 0) ? 1 : ((cls == 3) ? 4 : 2);
    const int T   = (cls == 0) ? 16 : ((cls == 3) ? 4 : 8);   // 128-key tiles

    const size_t base = (size_t)bz * 2048 * TOK + (size_t)h * 64;
    const float* qb = qg + base;
    float*       ob = outg + base;
    const __half* k16 = g_k16 + base;    // same linear layout as f32 inputs
    const __half* v16 = g_v16 + base;

    // ---- cp.async geometry: r = tid>>3 (0..15), chunk c = tid&7 ----
    // Each thread covers K rows {r + 16*it, it<8} and same V rows, 16B per op.
    const int c  = tid & 7;
    const int r  = tid >> 3;
    const size_t goff0 = (size_t)(k_start + r * dil) * TOK + c * 8;    // halfs
    const size_t cstep = (size_t)16 * dil * TOK;   // +16 rows
    const size_t tstep = (size_t)BN * dil * TOK;   // +128 rows (next tile)
    const uint32_t sKd = sb + SM_K + (uint32_t)(r * STRIDE * 2 + c * 16);
    const uint32_t sVd = sb + SM_V + (uint32_t)(r * STRIDE * 2 + c * 16);
    const uint32_t chstep = 16 * STRIDE * 2;       // +16 rows in smem (2304)
    const uint32_t hbuf = 128 * STRIDE * 2;        // f16 buffer stride (18432)
    const uint32_t halfb = 64 * STRIDE * 2;        // 64-key half stride (9216)

    // ---- issue tile 0 loads immediately (buf 0) ----
    {
        #pragma unroll
        for (int it = 0; it < 8; it++) {
            cpa16(sKd + it * chstep, k16 + goff0 + it * cstep);
            cpa16(sVd + it * chstep, v16 + goff0 + it * cstep);
        }
        cpa_commit();
    }

    // ---- stage Q tile as fp16 (pre-scaled) ----
    #pragma unroll 4
    for (int idx = tid; idx < BM * 16; idx += NTH) {
        int rr = idx >> 4, jj = idx & 15;
        int m = q_start + (qtile * BM + rr) * dil;
        float4 qv = *(const float4*)(qb + (size_t)m * TOK + jj * 4);
        sts64(sb + SM_Q + (uint32_t)(rr * STRIDE + jj * 4) * 2,
              f16x2(qv.y * QSCALE, qv.x * QSCALE),
              f16x2(qv.w * QSCALE, qv.z * QSCALE));
    }
    __syncthreads();   // Q visible

    // ---- Q a-fragments for BOTH m16 subtiles of this warp ----
    const int lq = lane >> 3;
    const int r8 = lane & 7;
    const int rowb = ((lq & 1) * 8) + r8;    // row within 16-block
    const int colq = (lq >> 1) * 8;          // col offset within 16-block
    uint32_t qaA[4][4], qaB[4][4];
    {
        uint32_t qaddrA = sb + SM_Q +
            (uint32_t)((wid * 32 + rowb) * STRIDE + colq) * 2;
        uint32_t qaddrB = qaddrA + 16 * STRIDE * 2;
        #pragma unroll
        for (int ks = 0; ks < 4; ks++) {
            ldmx4(qaA[ks], qaddrA + ks * 32);
            ldmx4(qaB[ks], qaddrB + ks * 32);
        }
    }

    float oA[8][4], oB[8][4];
    #pragma unroll
    for (int i = 0; i < 8; i++)
        #pragma unroll
        for (int jj = 0; jj < 4; jj++) { oA[i][jj] = 0.f; oB[i][jj] = 0.f; }
    float lfA[4] = {0.f, 0.f, 0.f, 0.f};
    float lfB[4] = {0.f, 0.f, 0.f, 0.f};

    const uint32_t kh32 = sb + SM_K + (uint32_t)(rowb * STRIDE + colq) * 2;
    const uint32_t vh32 = sb + SM_V + (uint32_t)(rowb * STRIDE + colq) * 2;

    for (int t = 0; t < T; t++) {
        cpa_wait<0>();     // tile t's 128 f16 rows landed
        __syncthreads();   // visible to all; prev compute done with other buf

        // ---- issue cp.async for tile t+1 into the other buffer ----
        if (t + 1 < T) {
            const __half* kp = k16 + goff0 + (size_t)(t + 1) * tstep;
            const __half* vp = v16 + goff0 + (size_t)(t + 1) * tstep;
            uint32_t bo = ((t + 1) & 1) * hbuf;
            #pragma unroll
            for (int it = 0; it < 8; it++) {
                cpa16(sKd + bo + it * chstep, kp + it * cstep);
                cpa16(sVd + bo + it * chstep, vp + it * cstep);
            }
            cpa_commit();
        }

        // ---- two 64-key halves, no barrier between them ----
        #pragma unroll
        for (int hh = 0; hh < 2; hh++) {
            const uint32_t kt32 = kh32 + (t & 1) * hbuf + hh * halfb;
            const uint32_t vt32 = vh32 + (t & 1) * hbuf + hh * halfb;

            // PHASE 1: S for both subtiles (accum init = -SHIFT)
            float sA[8][4], sB[8][4];
            #pragma unroll
            for (int i = 0; i < 8; i++)
                #pragma unroll
                for (int q4 = 0; q4 < 4; q4++) { sA[i][q4] = -SHIFT; sB[i][q4] = -SHIFT; }
            #pragma unroll
            for (int kg = 0; kg < 4; kg++) {
                #pragma unroll
                for (int ks = 0; ks < 4; ks++) {
                    uint32_t bk[4];
                    ldmx4(bk, kt32 + (uint32_t)(kg * 16 * STRIDE + ks * 16) * 2);
                    mma16816(sA[2 * kg],     qaA[ks], bk[0], bk[2]);
                    mma16816(sA[2 * kg + 1], qaA[ks], bk[1], bk[3]);
                    mma16816(sB[2 * kg],     qaB[ks], bk[0], bk[2]);
                    mma16816(sB[2 * kg + 1], qaB[ks], bk[1], bk[3]);
                }
            }

            // PHASE 2: softmax (MUFU pipelined) + l row sums
            uint32_t paA[4][4], paB[4][4];
            #pragma unroll
            for (int kg = 0; kg < 4; kg++) {
                const float* a0 = sA[2 * kg];
                const float* a1 = sA[2 * kg + 1];
                paA[kg][0] = f16x2(ex2(a0[1]), ex2(a0[0]));
                paA[kg][1] = f16x2(ex2(a0[3]), ex2(a0[2]));
                paA[kg][2] = f16x2(ex2(a1[1]), ex2(a1[0]));
                paA[kg][3] = f16x2(ex2(a1[3]), ex2(a1[2]));
                mma16816(lfA, paA[kg], ONESH2, ONESH2);
                const float* b0 = sB[2 * kg];
                const float* b1 = sB[2 * kg + 1];
                paB[kg][0] = f16x2(ex2(b0[1]), ex2(b0[0]));
                paB[kg][1] = f16x2(ex2(b0[3]), ex2(b0[2]));
                paB[kg][2] = f16x2(ex2(b1[1]), ex2(b1[0]));
                paB[kg][3] = f16x2(ex2(b1[3]), ex2(b1[2]));
                mma16816(lfB, paB[kg], ONESH2, ONESH2);
            }

            // PHASE 3: O += P*V
            #pragma unroll
            for (int kg = 0; kg < 4; kg++) {
                #pragma unroll
                for (int g = 0; g < 4; g++) {
                    uint32_t bv[4];
                    ldmx4t(bv, vt32 + (uint32_t)(kg * 16 * STRIDE + g * 16) * 2);
                    mma16816(oA[2 * g],     paA[kg], bv[0], bv[1]);
                    mma16816(oA[2 * g + 1], paA[kg], bv[2], bv[3]);
                    mma16816(oB[2 * g],     paB[kg], bv[0], bv[1]);
                    mma16816(oB[2 * g + 1], paB[kg], bv[2], bv[3]);
                }
            }
        }
    }

    // ---- epilogue: red.global.add.v2.f32 into out (pre-zeroed) ----
    const float invA0 = 1.f / lfA[0];
    const float invA1 = 1.f / lfA[2];
    const float invB0 = 1.f / lfB[0];
    const float invB1 = 1.f / lfB[2];
    const int rr = lane >> 2;
    const int cb = (lane & 3) * 2;
    const int i0 = qtile * BM + wid * 32 + rr;   // row index within component
    float* d0 = ob + (size_t)(q_start + i0 * dil) * TOK;
    float* d1 = ob + (size_t)(q_start + (i0 + 8) * dil) * TOK;
    float* d2 = ob + (size_t)(q_start + (i0 + 16) * dil) * TOK;
    float* d3 = ob + (size_t)(q_start + (i0 + 24) * dil) * TOK;
    #pragma unroll
    for (int nt = 0; nt < 8; nt++) {
        int col = nt * 8 + cb;
        red2(d0 + col, oA[nt][0] * invA0, oA[nt][1] * invA0);
        red2(d1 + col, oA[nt][2] * invA1, oA[nt][3] * invA1);
        red2(d2 + col, oB[nt][0] * invB0, oB[nt][1] * invB0);
        red2(d3 + col, oB[nt][2] * invB1, oB[nt][3] * invB1);
    }
}

extern "C" void kernel_launch(void* const* d_in, const int* in_sizes, int n_in,
                              void* d_out, int out_size) {
    const float* q = (const float*)d_in[0];
    const float* k = (const float*)d_in[1];
    const float* v = (const float*)d_in[2];
    float* out = (float*)d_out;

    const int H = 8;
    const int B = in_sizes[0] / (2048 * H * 64);

    cudaFuncSetAttribute(fa_dil, cudaFuncAttributeMaxDynamicSharedMemorySize, SM_TOT);

    // 1) convert K,V to f16 once + zero-fill out
    const int total8 = B * 2048 * TOK / 8;     // 16B chunks per f32 tensor
    const int total4 = B * 2048 * 128;         // 16B chunks of out
    const int nthread = 2 * total8 + total4;
    prepass<<<(nthread + 255) / 256, 256>>>((const float4*)k, (const float4*)v,
                                            (float4*)out, total8, total4);

    // 2) fused attention: all classes RED-accumulate into out
    fa_dil<<<dim3(B * H, 28), NTH, SM_TOT>>>(q, out);
}

// round 17
// speedup vs baseline: 1.0629x; 1.0629x over previous
#include <cuda_runtime.h>
#include <cuda_fp16.h>
#include <cstdint>

// ---------------------------------------------------------------------------
// Dilated attention = sum of 4 dense flash-attention sub-problems over strided
// row subsets (B=2, S=2048, H=8, D=64):
//   cls0: q_start=0,    k_start=0, dil=1, rows=2048, Nk=2048
//   cls1: q_start=0,    k_start=0, dil=2, rows=512,  Nk=1024
//   cls2: q_start=1025, k_start=1, dil=2, rows=512,  Nk=1024
//   cls3: q_start=0,    k_start=0, dil=4, rows=512,  Nk=512
// prepass: K/V -> f16 once AND zero-fills out. fa_dil: all classes accumulate
// straight into out with red.global.add.v2.f32 (no scratch, no combine pass).
// BN=64 tiles, one wait+barrier each (round-14 body: fits registers, no spill;
// the BN=128 unrolled variant hit the 256-reg cap and spilled -> reverted).
// 4 warps x 32 q-rows (two m16 subtiles per warp), mma.sync m16n8k16 fp16
// (fp32 accum), fixed-shift softmax, ones-MMA row sums.
// ---------------------------------------------------------------------------

#define TOK    512        // H*D elements per token (f32 in, f16 in g_k16/v16)
#define BM     128        // queries per CTA (4 warps x 32 rows)
#define BN     64         // keys per tile
#define NTH    128
#define STRIDE 72         // halfs per f16 smem row (conflict-free ldmatrix)

// dynamic smem layout (bytes)
#define SM_Q    0                                  // 128*72*2     = 18432
#define SM_K    18432                              // 2 * 64*72*2  = 18432
#define SM_V    (SM_K + 18432)                     // 18432
#define SM_TOT  (SM_V + 18432)                     // 55296

#define QSCALE 0.18033688f    // 0.125 * log2(e)
#define SHIFT  8.65617025f    // 6 * log2(e)
#define ONESH2 0x3C003C00u    // half2(1.0, 1.0)

// f16 copies of K and V (same [B,S,H,D] linear layout as the f32 inputs)
__device__ __half g_k16[2 * 2048 * 8 * 64];
__device__ __half g_v16[2 * 2048 * 8 * 64];

// ---- helpers --------------------------------------------------------------
__device__ __forceinline__ uint32_t smem_u32(const void* p) {
    uint32_t a;
    asm("{ .reg .u64 t; cvta.to.shared.u64 t, %1; cvt.u32.u64 %0, t; }"
        : "=r"(a) : "l"(p));
    return a;
}
__device__ __forceinline__ float ex2(float x) {
    float y; asm("ex2.approx.ftz.f32 %0, %1;" : "=f"(y) : "f"(x)); return y;
}
__device__ __forceinline__ uint32_t f16x2(float hi, float lo) {
    uint32_t r;
    asm("cvt.rn.f16x2.f32 %0, %1, %2;" : "=r"(r) : "f"(hi), "f"(lo));
    return r;
}
__device__ __forceinline__ void red2(float* a, float x, float y) {
    asm volatile("red.global.add.v2.f32 [%0], {%1, %2};"
                 :: "l"(a), "f"(x), "f"(y) : "memory");
}
__device__ __forceinline__ void cpa16(uint32_t saddr, const void* gaddr) {
    asm volatile("cp.async.cg.shared.global [%0], [%1], 16;"
                 :: "r"(saddr), "l"(gaddr));
}
__device__ __forceinline__ void cpa_commit() {
    asm volatile("cp.async.commit_group;");
}
template <int N> __device__ __forceinline__ void cpa_wait() {
    asm volatile("cp.async.wait_group %0;" :: "n"(N));
}
__device__ __forceinline__ void sts64(uint32_t a, uint32_t x, uint32_t y) {
    asm volatile("st.shared.v2.b32 [%0], {%1, %2};" :: "r"(a), "r"(x), "r"(y));
}
__device__ __forceinline__ void ldmx4(uint32_t r[4], uint32_t a) {
    asm volatile("ldmatrix.sync.aligned.m8n8.x4.shared.b16 {%0,%1,%2,%3}, [%4];"
        : "=r"(r[0]), "=r"(r[1]), "=r"(r[2]), "=r"(r[3]) : "r"(a));
}
__device__ __forceinline__ void ldmx4t(uint32_t r[4], uint32_t a) {
    asm volatile("ldmatrix.sync.aligned.m8n8.x4.trans.shared.b16 {%0,%1,%2,%3}, [%4];"
        : "=r"(r[0]), "=r"(r[1]), "=r"(r[2]), "=r"(r[3]) : "r"(a));
}
__device__ __forceinline__ void mma16816(float c[4], const uint32_t a[4],
                                         uint32_t b0, uint32_t b1) {
    asm volatile(
        "mma.sync.aligned.m16n8k16.row.col.f32.f16.f16.f32 "
        "{%0,%1,%2,%3}, {%4,%5,%6,%7}, {%8,%9}, {%0,%1,%2,%3};"
        : "+f"(c[0]), "+f"(c[1]), "+f"(c[2]), "+f"(c[3])
        : "r"(a[0]), "r"(a[1]), "r"(a[2]), "r"(a[3]), "r"(b0), "r"(b1));
}

// ---- pre-pass: K/V f32->f16 convert + zero-fill out -----------------------
__global__ void __launch_bounds__(256)
prepass(const float4* __restrict__ k, const float4* __restrict__ v,
        float4* __restrict__ out, int total8, int total4)
{
    int i = blockIdx.x * 256 + threadIdx.x;
    if (i < 2 * total8) {                      // convert K or V (16B chunk)
        bool isV = i >= total8;
        int jj = isV ? i - total8 : i;
        const float4* s = (isV ? v : k) + (size_t)jj * 2;
        float4 a = s[0], b = s[1];
        uint4 o;
        o.x = f16x2(a.y, a.x); o.y = f16x2(a.w, a.z);
        o.z = f16x2(b.y, b.x); o.w = f16x2(b.w, b.z);
        ((uint4*)(isV ? g_v16 : g_k16))[jj] = o;
    } else {                                   // zero 16B of out
        int jj = i - 2 * total8;
        if (jj < total4) out[jj] = make_float4(0.f, 0.f, 0.f, 0.f);
    }
}

// ---------------------------------------------------------------------------

__global__ void __launch_bounds__(NTH, 2)
fa_dil(const float* __restrict__ qg, float* __restrict__ outg)
{
    extern __shared__ char smem[];
    const uint32_t sb = smem_u32(smem);

    const int tid = threadIdx.x;
    const int wid = tid >> 5;            // 0..3, owns rows wid*32..wid*32+31
    const int lane = tid & 31;
    const int by = blockIdx.y;           // class/qtile (cls0 lowest bids)
    const int bz = blockIdx.x >> 3;      // H = 8
    const int h  = blockIdx.x & 7;

    // ---- decode component class ----
    int cls, qtile;
    if (by < 16)      { cls = 0; qtile = by; }
    else if (by < 20) { cls = 1; qtile = by - 16; }
    else if (by < 24) { cls = 2; qtile = by - 20; }
    else              { cls = 3; qtile = by - 24; }
    const int q_start = (cls == 2) ? 1025 : 0;
    const int k_start = (cls == 2) ? 1 : 0;
    const int dil = (cls == 0) ? 1 : ((cls == 3) ? 4 : 2);
    const int T   = (cls == 0) ? 32 : ((cls == 3) ? 8 : 16);

    const size_t base = (size_t)bz * 2048 * TOK + (size_t)h * 64;
    const float* qb = qg + base;
    float*       ob = outg + base;
    const __half* k16 = g_k16 + base;    // same linear layout as f32 inputs
    const __half* v16 = g_v16 + base;

    // ---- cp.async geometry: r = tid>>3 (0..15), chunk c = tid&7 ----
    // Each thread covers K rows {r + 16*it, it<4} and same V rows, 16B per op.
    const int c  = tid & 7;
    const int r  = tid >> 3;
    const size_t goff0 = (size_t)(k_start + r * dil) * TOK + c * 8;    // halfs
    const size_t cstep = (size_t)16 * dil * TOK;   // +16 rows
    const size_t tstep = (size_t)BN * dil * TOK;   // +64 rows (next tile)
    const uint32_t sKd = sb + SM_K + (uint32_t)(r * STRIDE * 2 + c * 16);
    const uint32_t sVd = sb + SM_V + (uint32_t)(r * STRIDE * 2 + c * 16);
    const uint32_t chstep = 16 * STRIDE * 2;       // +16 rows in smem (2304)
    const uint32_t hbuf = 64 * STRIDE * 2;         // f16 buffer stride (9216)

    // ---- issue tile 0 loads immediately (buf 0) ----
    {
        #pragma unroll
        for (int it = 0; it < 4; it++) {
            cpa16(sKd + it * chstep, k16 + goff0 + it * cstep);
            cpa16(sVd + it * chstep, v16 + goff0 + it * cstep);
        }
        cpa_commit();
    }

    // ---- stage Q tile as fp16 (pre-scaled) ----
    #pragma unroll 4
    for (int idx = tid; idx < BM * 16; idx += NTH) {
        int rr = idx >> 4, jj = idx & 15;
        int m = q_start + (qtile * BM + rr) * dil;
        float4 qv = *(const float4*)(qb + (size_t)m * TOK + jj * 4);
        sts64(sb + SM_Q + (uint32_t)(rr * STRIDE + jj * 4) * 2,
              f16x2(qv.y * QSCALE, qv.x * QSCALE),
              f16x2(qv.w * QSCALE, qv.z * QSCALE));
    }
    __syncthreads();   // Q visible

    // ---- Q a-fragments for BOTH m16 subtiles of this warp ----
    const int lq = lane >> 3;
    const int r8 = lane & 7;
    const int rowb = ((lq & 1) * 8) + r8;    // row within 16-block
    const int colq = (lq >> 1) * 8;          // col offset within 16-block
    uint32_t qaA[4][4], qaB[4][4];
    {
        uint32_t qaddrA = sb + SM_Q +
            (uint32_t)((wid * 32 + rowb) * STRIDE + colq) * 2;
        uint32_t qaddrB = qaddrA + 16 * STRIDE * 2;
        #pragma unroll
        for (int ks = 0; ks < 4; ks++) {
            ldmx4(qaA[ks], qaddrA + ks * 32);
            ldmx4(qaB[ks], qaddrB + ks * 32);
        }
    }

    float oA[8][4], oB[8][4];
    #pragma unroll
    for (int i = 0; i < 8; i++)
        #pragma unroll
        for (int jj = 0; jj < 4; jj++) { oA[i][jj] = 0.f; oB[i][jj] = 0.f; }
    float lfA[4] = {0.f, 0.f, 0.f, 0.f};
    float lfB[4] = {0.f, 0.f, 0.f, 0.f};

    const uint32_t kh32 = sb + SM_K + (uint32_t)(rowb * STRIDE + colq) * 2;
    const uint32_t vh32 = sb + SM_V + (uint32_t)(rowb * STRIDE + colq) * 2;

    for (int t = 0; t < T; t++) {
        cpa_wait<0>();     // tile t's f16 rows landed
        __syncthreads();   // visible to all; prev compute done with other buf

        // ---- issue cp.async for tile t+1 into the other buffer ----
        if (t + 1 < T) {
            const __half* kp = k16 + goff0 + (size_t)(t + 1) * tstep;
            const __half* vp = v16 + goff0 + (size_t)(t + 1) * tstep;
            uint32_t bo = ((t + 1) & 1) * hbuf;
            #pragma unroll
            for (int it = 0; it < 4; it++) {
                cpa16(sKd + bo + it * chstep, kp + it * cstep);
                cpa16(sVd + bo + it * chstep, vp + it * cstep);
            }
            cpa_commit();
        }

        const uint32_t kt32 = kh32 + (t & 1) * hbuf;
        const uint32_t vt32 = vh32 + (t & 1) * hbuf;

        // ---- PHASE 1: S for both subtiles (accum init = -SHIFT) ----
        float sA[8][4], sB[8][4];
        #pragma unroll
        for (int i = 0; i < 8; i++)
            #pragma unroll
            for (int q4 = 0; q4 < 4; q4++) { sA[i][q4] = -SHIFT; sB[i][q4] = -SHIFT; }
        #pragma unroll
        for (int kg = 0; kg < 4; kg++) {
            #pragma unroll
            for (int ks = 0; ks < 4; ks++) {
                uint32_t bk[4];
                ldmx4(bk, kt32 + (uint32_t)(kg * 16 * STRIDE + ks * 16) * 2);
                mma16816(sA[2 * kg],     qaA[ks], bk[0], bk[2]);
                mma16816(sA[2 * kg + 1], qaA[ks], bk[1], bk[3]);
                mma16816(sB[2 * kg],     qaB[ks], bk[0], bk[2]);
                mma16816(sB[2 * kg + 1], qaB[ks], bk[1], bk[3]);
            }
        }

        // ---- PHASE 2: softmax (MUFU pipelined) + l row sums ----
        uint32_t paA[4][4], paB[4][4];
        #pragma unroll
        for (int kg = 0; kg < 4; kg++) {
            const float* a0 = sA[2 * kg];
            const float* a1 = sA[2 * kg + 1];
            paA[kg][0] = f16x2(ex2(a0[1]), ex2(a0[0]));
            paA[kg][1] = f16x2(ex2(a0[3]), ex2(a0[2]));
            paA[kg][2] = f16x2(ex2(a1[1]), ex2(a1[0]));
            paA[kg][3] = f16x2(ex2(a1[3]), ex2(a1[2]));
            mma16816(lfA, paA[kg], ONESH2, ONESH2);
            const float* b0 = sB[2 * kg];
            const float* b1 = sB[2 * kg + 1];
            paB[kg][0] = f16x2(ex2(b0[1]), ex2(b0[0]));
            paB[kg][1] = f16x2(ex2(b0[3]), ex2(b0[2]));
            paB[kg][2] = f16x2(ex2(b1[1]), ex2(b1[0]));
            paB[kg][3] = f16x2(ex2(b1[3]), ex2(b1[2]));
            mma16816(lfB, paB[kg], ONESH2, ONESH2);
        }

        // ---- PHASE 3: O += P*V ----
        #pragma unroll
        for (int kg = 0; kg < 4; kg++) {
            #pragma unroll
            for (int g = 0; g < 4; g++) {
                uint32_t bv[4];
                ldmx4t(bv, vt32 + (uint32_t)(kg * 16 * STRIDE + g * 16) * 2);
                mma16816(oA[2 * g],     paA[kg], bv[0], bv[1]);
                mma16816(oA[2 * g + 1], paA[kg], bv[2], bv[3]);
                mma16816(oB[2 * g],     paB[kg], bv[0], bv[1]);
                mma16816(oB[2 * g + 1], paB[kg], bv[2], bv[3]);
            }
        }
    }

    // ---- epilogue: red.global.add.v2.f32 into out (pre-zeroed) ----
    const float invA0 = 1.f / lfA[0];
    const float invA1 = 1.f / lfA[2];
    const float invB0 = 1.f / lfB[0];
    const float invB1 = 1.f / lfB[2];
    const int rr = lane >> 2;
    const int cb = (lane & 3) * 2;
    const int i0 = qtile * BM + wid * 32 + rr;   // row index within component
    float* d0 = ob + (size_t)(q_start + i0 * dil) * TOK;
    float* d1 = ob + (size_t)(q_start + (i0 + 8) * dil) * TOK;
    float* d2 = ob + (size_t)(q_start + (i0 + 16) * dil) * TOK;
    float* d3 = ob + (size_t)(q_start + (i0 + 24) * dil) * TOK;
    #pragma unroll
    for (int nt = 0; nt < 8; nt++) {
        int col = nt * 8 + cb;
        red2(d0 + col, oA[nt][0] * invA0, oA[nt][1] * invA0);
        red2(d1 + col, oA[nt][2] * invA1, oA[nt][3] * invA1);
        red2(d2 + col, oB[nt][0] * invB0, oB[nt][1] * invB0);
        red2(d3 + col, oB[nt][2] * invB1, oB[nt][3] * invB1);
    }
}

extern "C" void kernel_launch(void* const* d_in, const int* in_sizes, int n_in,
                              void* d_out, int out_size) {
    const float* q = (const float*)d_in[0];
    const float* k = (const float*)d_in[1];
    const float* v = (const float*)d_in[2];
    float* out = (float*)d_out;

    const int H = 8;
    const int B = in_sizes[0] / (2048 * H * 64);

    cudaFuncSetAttribute(fa_dil, cudaFuncAttributeMaxDynamicSharedMemorySize, SM_TOT);

    // 1) convert K,V to f16 once + zero-fill out
    const int total8 = B * 2048 * TOK / 8;     // 16B chunks per f32 tensor
    const int total4 = B * 2048 * 128;         // 16B chunks of out
    const int nthread = 2 * total8 + total4;
    prepass<<<(nthread + 255) / 256, 256>>>((const float4*)k, (const float4*)v,
                                            (float4*)out, total8, total4);

    // 2) fused attention: all classes RED-accumulate into out
    fa_dil<<<dim3(B * H, 28), NTH, SM_TOT>>>(q, out);
}